// round 6
// baseline (speedup 1.0000x reference)
#include <cuda_runtime.h>
#include <cstdint>

#define BB 4
#define NP 8192
#define MP 2048          // NP/4
#define KNN 16
#define CIN 64
#define CO 128
#define CG 67            // 3 + CIN
#define CGP 68           // padded
#define EPSBN 1e-5
#define FTH 512          // FPS threads
#define FPT 16           // points per thread (512*16 = 8192)
#define NWARP (FTH/32)   // 16

// ---------------- scratch (static device allocations are allowed) -------------
__device__ float  g_newp[BB * MP * 3];
__device__ float4 g_pts4[BB * NP];
__device__ int    g_nidx[BB * MP * KNN];
__device__ float  g_ymax[BB * MP * CO];
__device__ float  g_ymin[BB * MP * CO];
__device__ double g_sum[CO];
__device__ double g_sumsq[CO];
__device__ float  g_scale[CO];
__device__ float  g_meanv[CO];
__device__ float  g_shift[CO];

// ---------------- init: zero the BN accumulators (every replay) ----------------
__global__ void init_kernel() {
    int t = threadIdx.x;
    if (t < CO) { g_sum[t] = 0.0; g_sumsq[t] = 0.0; }
}

// ---------------- precompute (x,y,z,|p|^2) per point ---------------------------
__global__ void prep_kernel(const float* __restrict__ pt) {
    int i = blockIdx.x * 256 + threadIdx.x;
    if (i >= BB * NP) return;
    float x = pt[3 * i], y = pt[3 * i + 1], z = pt[3 * i + 2];
    // JAX: sum(p*p, -1) == (x*x + y*y) + z*z, no fma contraction
    float pp = __fadd_rn(__fadd_rn(__fmul_rn(x, x), __fmul_rn(y, y)), __fmul_rn(z, z));
    g_pts4[i] = make_float4(x, y, z, pp);
}

// ---------------- packed f32x2 helpers (bit-exact .rn per-lane ops) -------------
__device__ __forceinline__ unsigned long long f32x2_pack(float lo, float hi) {
    unsigned long long r;
    asm("mov.b64 %0, {%1, %2};" : "=l"(r) : "f"(lo), "f"(hi));
    return r;
}
__device__ __forceinline__ unsigned long long f32x2_add(unsigned long long a,
                                                        unsigned long long b) {
    unsigned long long r;
    asm("add.rn.f32x2 %0, %1, %2;" : "=l"(r) : "l"(a), "l"(b));
    return r;
}
__device__ __forceinline__ unsigned long long f32x2_mul(unsigned long long a,
                                                        unsigned long long b) {
    unsigned long long r;
    asm("mul.rn.f32x2 %0, %1, %2;" : "=l"(r) : "l"(a), "l"(b));
    return r;
}
__device__ __forceinline__ void f32x2_unpack(unsigned long long v, float& lo, float& hi) {
    asm("mov.b64 {%0, %1}, %2;" : "=f"(lo), "=f"(hi) : "l"(v));
}

// ---------------- FPS: one CTA/batch, 512 thr, tree argmax, float4 coords -------
extern __shared__ float4 fps_sp4[];   // 8192 * 16B = 128 KB
__global__ void __launch_bounds__(FTH, 1) fps_kernel() {
    __shared__ uint2 s_lead[2][NWARP];

    const int t = threadIdx.x;
    const int b = blockIdx.x;
    const float4* P4 = g_pts4 + (size_t)b * NP;
    const int base = t * FPT;

    // stage coords: packed register pairs + float4 smem table for winner lookup
    unsigned long long pxp[FPT / 2], pyp[FPT / 2], pzp[FPT / 2];
    float dist[FPT];
#pragma unroll
    for (int j = 0; j < FPT / 2; j++) {
        float4 v0 = P4[base + 2 * j];
        float4 v1 = P4[base + 2 * j + 1];
        fps_sp4[base + 2 * j]     = make_float4(v0.x, v0.y, v0.z, 0.f);
        fps_sp4[base + 2 * j + 1] = make_float4(v1.x, v1.y, v1.z, 0.f);
        pxp[j] = f32x2_pack(v0.x, v1.x);
        pyp[j] = f32x2_pack(v0.y, v1.y);
        pzp[j] = f32x2_pack(v0.z, v1.z);
        dist[2 * j] = 1e10f; dist[2 * j + 1] = 1e10f;
    }

    float4 q0 = __ldg(P4);
    float qx = q0.x, qy = q0.y, qz = q0.z;
    if (t == 0) {
        int o = (b * MP) * 3;
        g_newp[o] = qx; g_newp[o + 1] = qy; g_newp[o + 2] = qz;
    }
    __syncthreads();

    const int lane = t & 31;
    const int wrp = t >> 5;

    for (int it = 1; it < MP; it++) {
        const int buf = it & 1;
        // p - q == p + (-q), bit-exact .rn
        const unsigned long long nqx2 = f32x2_pack(-qx, -qx);
        const unsigned long long nqy2 = f32x2_pack(-qy, -qy);
        const unsigned long long nqz2 = f32x2_pack(-qz, -qz);

        // ---- distance update (fma pipe) ----
#pragma unroll
        for (int j = 0; j < FPT / 2; j++) {
            unsigned long long dx = f32x2_add(pxp[j], nqx2);
            unsigned long long dy = f32x2_add(pyp[j], nqy2);
            unsigned long long dz = f32x2_add(pzp[j], nqz2);
            unsigned long long t1 = f32x2_mul(dx, dx);
            unsigned long long t2 = f32x2_mul(dy, dy);
            unsigned long long s1 = f32x2_add(t1, t2);
            unsigned long long t3 = f32x2_mul(dz, dz);
            unsigned long long dd = f32x2_add(s1, t3);
            float d0, d1;
            f32x2_unpack(dd, d0, d1);
            dist[2 * j]     = fminf(dist[2 * j], d0);
            dist[2 * j + 1] = fminf(dist[2 * j + 1], d1);
        }

        // ---- per-thread argmax: fmax tree + integer-equality mask (parallel) ----
        float m8[8];
#pragma unroll
        for (int i = 0; i < 8; i++) m8[i] = fmaxf(dist[2 * i], dist[2 * i + 1]);
        float m4a = fmaxf(m8[0], m8[1]), m4b = fmaxf(m8[2], m8[3]);
        float m4c = fmaxf(m8[4], m8[5]), m4d = fmaxf(m8[6], m8[7]);
        float bv = fmaxf(fmaxf(m4a, m4b), fmaxf(m4c, m4d));
        uint32_t bvbits = __float_as_uint(bv);       // dists >= +0: bits monotone & exact
        uint32_t mask = 0;
#pragma unroll
        for (int i = 0; i < FPT; i++)
            mask |= (__float_as_uint(dist[i]) == bvbits) ? (1u << i) : 0u;
        int bi = base + (__ffs(mask) - 1);           // lowest local index on ties

        // ---- warp argmax via REDUX (lane order == index order) ----
        uint32_t mx = __reduce_max_sync(0xffffffffu, bvbits);
        uint32_t ball = __ballot_sync(0xffffffffu, bvbits == mx);
        int wbi = __shfl_sync(0xffffffffu, bi, __ffs(ball) - 1);
        if (lane == 0) s_lead[buf][wrp] = make_uint2(mx, (uint32_t)wbi);
        __syncthreads();

        // ---- stage 2: every warp reduces the 16 leaders itself (no 2nd barrier) ----
        uint2 L = (lane < NWARP) ? s_lead[buf][lane] : make_uint2(0u, 0u);
        uint32_t m2 = __reduce_max_sync(0xffffffffu, L.x);
        uint32_t b2 = __ballot_sync(0xffffffffu, L.x == m2);
        int w = __shfl_sync(0xffffffffu, (int)L.y, __ffs(b2) - 1);

        float4 qv = fps_sp4[w];                      // one broadcast LDS.128
        qx = qv.x; qy = qv.y; qz = qv.z;
        if (t == 0) {
            int o = (b * MP + it) * 3;
            g_newp[o] = qx; g_newp[o + 1] = qy; g_newp[o + 2] = qz;
        }
    }
}

// ---------------- KNN: thread-per-query, 16-entry register heap ----------------
#define KT 2048   // point tile
__global__ void __launch_bounds__(128) knn_kernel() {
    __shared__ __align__(16) float4 tile[KT];
    const int m = blockIdx.x * 128 + threadIdx.x;       // global query id
    const int b = m / MP;

    const float q0 = g_newp[3 * m], q1 = g_newp[3 * m + 1], q2 = g_newp[3 * m + 2];
    const float qq = __fadd_rn(__fadd_rn(__fmul_rn(q0, q0), __fmul_rn(q1, q1)),
                               __fmul_rn(q2, q2));

    float bd[KNN]; int bix[KNN];
#pragma unroll
    for (int s = 0; s < KNN; s++) { bd[s] = 3.402823466e38f; bix[s] = 0x7fffffff; }
    float wv = 3.402823466e38f; int wIdx = 0x7fffffff; int wslot = 0;

    const float4* src = g_pts4 + (size_t)b * NP;
    for (int tb = 0; tb < NP / KT; tb++) {
        for (int j = threadIdx.x; j < KT; j += 128) tile[j] = src[tb * KT + j];
        __syncthreads();
        for (int jj = 0; jj < KT; jj++) {
            float4 p = tile[jj];
            // JAX: d2 = (qq + pp) - 2*(q . p)  with fma-chain dot
            float dot = __fmaf_rn(q2, p.z, __fmaf_rn(q1, p.y, __fmul_rn(q0, p.x)));
            float d2 = __fsub_rn(__fadd_rn(qq, p.w), __fmul_rn(2.0f, dot));
            if (d2 < wv) {                        // strict: ties keep earlier index
                int j = tb * KT + jj;
#pragma unroll
                for (int s = 0; s < KNN; s++)
                    if (s == wslot) { bd[s] = d2; bix[s] = j; }
                wv = bd[0]; wIdx = bix[0]; wslot = 0;
#pragma unroll
                for (int s = 1; s < KNN; s++)
                    if (bd[s] > wv || (bd[s] == wv && bix[s] > wIdx)) {
                        wv = bd[s]; wIdx = bix[s]; wslot = s;
                    }
            }
        }
        __syncthreads();
    }
#pragma unroll
    for (int s = 0; s < KNN; s++) g_nidx[m * KNN + s] = bix[s];
}

// ---------------- group + linear + channel stats + k-max/min -------------------
__global__ void __launch_bounds__(128) group_kernel(const float* __restrict__ feat,
                                                    const float* __restrict__ Wm) {
    __shared__ __align__(16) float sW[CO * CG];
    __shared__ __align__(16) float sg[KNN][CGP];
    __shared__ int snb[KNN];

    const int tid = threadIdx.x;
    const int o = tid;
    for (int j = tid; j < CO * CG; j += 128) sW[j] = Wm[j];
    __syncthreads();

    float w[CGP];
#pragma unroll
    for (int c = 0; c < CG; c++) w[c] = sW[o * CG + c];
    w[CG] = 0.0f;

    double lsum = 0.0, lsq = 0.0;
    const int m0 = blockIdx.x * 8;

    for (int mi = 0; mi < 8; mi++) {
        const int m = m0 + mi;
        const int b = m / MP;
        if (tid < KNN) snb[tid] = g_nidx[m * KNN + tid];
        __syncthreads();

        // relative xyz (JAX-exact sub) + zero pad
        if (tid < KNN) {
            float4 p = g_pts4[(size_t)b * NP + snb[tid]];
            sg[tid][0] = __fsub_rn(p.x, g_newp[3 * m]);
            sg[tid][1] = __fsub_rn(p.y, g_newp[3 * m + 1]);
            sg[tid][2] = __fsub_rn(p.z, g_newp[3 * m + 2]);
            sg[tid][CG] = 0.0f;
        }
        // features: 16 rows x 64, 8 floats per thread
        {
            int k = tid >> 3, c0 = (tid & 7) << 3;
            const float* fr = feat + ((size_t)b * NP + snb[k]) * CIN + c0;
            float4 a = *(const float4*)fr;
            float4 bq = *(const float4*)(fr + 4);
            sg[k][3 + c0 + 0] = a.x;  sg[k][3 + c0 + 1] = a.y;
            sg[k][3 + c0 + 2] = a.z;  sg[k][3 + c0 + 3] = a.w;
            sg[k][3 + c0 + 4] = bq.x; sg[k][3 + c0 + 5] = bq.y;
            sg[k][3 + c0 + 6] = bq.z; sg[k][3 + c0 + 7] = bq.w;
        }
        __syncthreads();

        float ymx = -3.402823466e38f, ymn = 3.402823466e38f;
#pragma unroll 1
        for (int k = 0; k < KNN; k++) {
            const float4* gr = (const float4*)sg[k];
            float acc = 0.0f;
#pragma unroll
            for (int c4 = 0; c4 < CGP / 4; c4++) {
                float4 gv = gr[c4];
                acc = __fmaf_rn(gv.x, w[4 * c4 + 0], acc);
                acc = __fmaf_rn(gv.y, w[4 * c4 + 1], acc);
                acc = __fmaf_rn(gv.z, w[4 * c4 + 2], acc);
                acc = __fmaf_rn(gv.w, w[4 * c4 + 3], acc);
            }
            ymx = fmaxf(ymx, acc);
            ymn = fminf(ymn, acc);
            lsum += (double)acc;
            lsq = fma((double)acc, (double)acc, lsq);
        }
        g_ymax[m * CO + o] = ymx;
        g_ymin[m * CO + o] = ymn;
        __syncthreads();
    }
    atomicAdd(&g_sum[o], lsum);
    atomicAdd(&g_sumsq[o], lsq);
}

// ---------------- BN statistics finalize ----------------------------------------
__global__ void stats_kernel(const float* __restrict__ gamma,
                             const float* __restrict__ beta) {
    int o = threadIdx.x;
    if (o >= CO) return;
    const double n = (double)BB * MP * KNN;
    double mean = g_sum[o] / n;
    double var = g_sumsq[o] / n - mean * mean;
    if (var < 0.0) var = 0.0;
    double s = (double)gamma[o] / sqrt(var + EPSBN);
    g_scale[o] = (float)s;
    g_meanv[o] = (float)mean;
    g_shift[o] = beta[o];
}

// ---------------- output: relu(max_k BN(y)) via max/min trick -------------------
__global__ void out_kernel(float* __restrict__ dst) {
    int idx = blockIdx.x * 256 + threadIdx.x;
    if (idx >= BB * MP * CO) return;
    int o = idx & (CO - 1);
    float s = g_scale[o];
    float v = (s >= 0.0f) ? g_ymax[idx] : g_ymin[idx];
    float t = __fsub_rn(v, g_meanv[o]);
    float r = __fadd_rn(__fmul_rn(t, s), g_shift[o]);
    dst[idx] = fmaxf(r, 0.0f);
}

__global__ void copy_np_kernel(float* __restrict__ dst) {
    int i = blockIdx.x * 256 + threadIdx.x;
    if (i < BB * MP * 3) dst[i] = g_newp[i];
}

__global__ void splits_f32_kernel(float* __restrict__ dst) {
    int i = threadIdx.x;
    if (i <= BB) dst[i] = (float)(i * MP);
}
__global__ void splits_i64_kernel(long long* __restrict__ dst) {
    int i = threadIdx.x;
    if (i <= BB) dst[i] = (long long)i * MP;
}

// ---------------- launch ---------------------------------------------------------
extern "C" void kernel_launch(void* const* d_in, const int* in_sizes, int n_in,
                              void* d_out, int out_size) {
    const float* point = (const float*)d_in[0];
    const float* feat  = (const float*)d_in[1];
    const float* Wm    = (const float*)d_in[3];
    const float* gamma = (const float*)d_in[4];
    const float* beta  = (const float*)d_in[5];
    float* out = (float*)d_out;

    const int FPS_SMEM = NP * 16;         // 128 KB dynamic (float4 per point)
    cudaFuncSetAttribute(fps_kernel, cudaFuncAttributeMaxDynamicSharedMemorySize, FPS_SMEM);

    init_kernel<<<1, 128>>>();
    prep_kernel<<<(BB * NP + 255) / 256, 256>>>(point);
    fps_kernel<<<BB, FTH, FPS_SMEM>>>();
    knn_kernel<<<BB * MP / 128, 128>>>();
    group_kernel<<<BB * MP / 8, 128>>>(feat, Wm);
    stats_kernel<<<1, 128>>>(gamma, beta);

    const int NPT = BB * MP * 3;          // 24576
    const int NFT = BB * MP * CO;         // 1048576
    int feat_off = 0;
    bool write_pts = false;
    if (out_size >= NPT + NFT) { write_pts = true; feat_off = NPT; }

    out_kernel<<<(NFT + 255) / 256, 256>>>(out + feat_off);
    if (write_pts) copy_np_kernel<<<(NPT + 255) / 256, 256>>>(out);

    int rem = out_size - feat_off - NFT;
    if (rem == BB + 1) {
        splits_f32_kernel<<<1, 32>>>(out + feat_off + NFT);
    } else if (rem == 2 * (BB + 1)) {
        splits_i64_kernel<<<1, 32>>>((long long*)(out + feat_off + NFT));
    }
}

// round 7
// speedup vs baseline: 1.0538x; 1.0538x over previous
#include <cuda_runtime.h>
#include <cstdint>

#define BB 4
#define NP 8192
#define MP 2048          // NP/4
#define KNN 16
#define CIN 64
#define CO 128
#define CG 67            // 3 + CIN
#define CGP 68           // padded
#define EPSBN 1e-5
#define CSZ 4            // FPS cluster CTAs per batch
#define FTH 256          // FPS threads per CTA
#define FPT 8            // points per thread (256*8*4 = 8192)
#define LPTS (FTH*FPT)   // 2048 points per CTA
#define NW (FTH/32)      // 8 warps

typedef unsigned long long u64;

// ---------------- scratch (static device allocations are allowed) -------------
__device__ float  g_newp[BB * MP * 3];
__device__ float4 g_pts4[BB * NP];
__device__ int    g_nidx[BB * MP * KNN];
__device__ float  g_ymax[BB * MP * CO];
__device__ float  g_ymin[BB * MP * CO];
__device__ double g_sum[CO];
__device__ double g_sumsq[CO];
__device__ float  g_scale[CO];
__device__ float  g_meanv[CO];
__device__ float  g_shift[CO];

// ---------------- init: zero the BN accumulators (every replay) ----------------
__global__ void init_kernel() {
    int t = threadIdx.x;
    if (t < CO) { g_sum[t] = 0.0; g_sumsq[t] = 0.0; }
}

// ---------------- precompute (x,y,z,|p|^2) per point ---------------------------
__global__ void prep_kernel(const float* __restrict__ pt) {
    int i = blockIdx.x * 256 + threadIdx.x;
    if (i >= BB * NP) return;
    float x = pt[3 * i], y = pt[3 * i + 1], z = pt[3 * i + 2];
    // JAX: sum(p*p, -1) == (x*x + y*y) + z*z, no fma contraction
    float pp = __fadd_rn(__fadd_rn(__fmul_rn(x, x), __fmul_rn(y, y)), __fmul_rn(z, z));
    g_pts4[i] = make_float4(x, y, z, pp);
}

// ---------------- helpers -------------------------------------------------------
__device__ __forceinline__ uint32_t smem_u32(const void* p) {
    return (uint32_t)__cvta_generic_to_shared(p);
}
__device__ __forceinline__ uint32_t ctarank() {
    uint32_t r; asm("mov.u32 %0, %%cluster_ctarank;" : "=r"(r)); return r;
}
__device__ __forceinline__ uint32_t mapa_rank(uint32_t addr, uint32_t r) {
    uint32_t out;
    asm("mapa.shared::cluster.u32 %0, %1, %2;" : "=r"(out) : "r"(addr), "r"(r));
    return out;
}
__device__ __forceinline__ void st_clu_u64(uint32_t a, u64 v) {
    asm volatile("st.shared::cluster.u64 [%0], %1;" :: "r"(a), "l"(v) : "memory");
}
__device__ __forceinline__ u64 ld_vol_sh_u64(uint32_t a) {
    u64 v;
    asm volatile("ld.volatile.shared.b64 %0, [%1];" : "=l"(v) : "r"(a) : "memory");
    return v;
}
__device__ __forceinline__ u64 f32x2_pack(float lo, float hi) {
    u64 r; asm("mov.b64 %0, {%1, %2};" : "=l"(r) : "f"(lo), "f"(hi)); return r;
}
__device__ __forceinline__ u64 f32x2_add(u64 a, u64 b) {
    u64 r; asm("add.rn.f32x2 %0, %1, %2;" : "=l"(r) : "l"(a), "l"(b)); return r;
}
__device__ __forceinline__ u64 f32x2_mul(u64 a, u64 b) {
    u64 r; asm("mul.rn.f32x2 %0, %1, %2;" : "=l"(r) : "l"(a), "l"(b)); return r;
}
__device__ __forceinline__ void f32x2_unpack(u64 v, float& lo, float& hi) {
    asm("mov.b64 {%0, %1}, %2;" : "=f"(lo), "=f"(hi) : "l"(v));
}

// ---------------- FPS: 4-CTA cluster, fence-free stamped exchange ---------------
__global__ void __cluster_dims__(CSZ, 1, 1) __launch_bounds__(FTH, 1)
fps_kernel() {
    __shared__ __align__(16) float4 s_p4[LPTS];          // 32 KB coord table
    __shared__ uint2 s_lead[2][NW];
    __shared__ __align__(8) u64 s_slot[2][CSZ][4];       // [buf][src rank][word]

    const int t = threadIdx.x;
    const int lane = t & 31;
    const int wrp = t >> 5;
    const uint32_t r = ctarank();
    const int b = blockIdx.x / CSZ;
    const float4* P4 = g_pts4 + (size_t)b * NP + (size_t)r * LPTS;
    const int base = t * FPT;                            // CTA-local point index

    if (t < 2 * CSZ * 4) ((u64*)s_slot)[t] = 0ull;       // stamp 0 != any it>=1

    // load my points: packed register pairs + float4 table
    u64 pxp[FPT / 2], pyp[FPT / 2], pzp[FPT / 2];
    float dist[FPT];
#pragma unroll
    for (int j = 0; j < FPT / 2; j++) {
        float4 v0 = P4[base + 2 * j];
        float4 v1 = P4[base + 2 * j + 1];
        s_p4[base + 2 * j]     = make_float4(v0.x, v0.y, v0.z, 0.f);
        s_p4[base + 2 * j + 1] = make_float4(v1.x, v1.y, v1.z, 0.f);
        pxp[j] = f32x2_pack(v0.x, v1.x);
        pyp[j] = f32x2_pack(v0.y, v1.y);
        pzp[j] = f32x2_pack(v0.z, v1.z);
        dist[2 * j] = 1e10f; dist[2 * j + 1] = 1e10f;
    }

    float4 q0 = __ldg(g_pts4 + (size_t)b * NP);          // global point 0
    float qx = q0.x, qy = q0.y, qz = q0.z;
    if (r == 0 && t == 0) {
        int o = (b * MP) * 3;
        g_newp[o] = qx; g_newp[o + 1] = qy; g_newp[o + 2] = qz;
    }

    // sender addresses (warp 0, lanes 0..15): dest CTA = lane/4, word = lane%4
    uint32_t a_s0 = 0, a_s1 = 0;
    if (t < 16) {
        a_s0 = mapa_rank(smem_u32(&s_slot[0][r][t & 3]), (uint32_t)(t >> 2));
        a_s1 = mapa_rank(smem_u32(&s_slot[1][r][t & 3]), (uint32_t)(t >> 2));
    }

    __syncthreads();
    asm volatile("barrier.cluster.arrive.aligned;" ::: "memory");
    asm volatile("barrier.cluster.wait.aligned;" ::: "memory");

    for (int it = 1; it < MP; it++) {
        const int buf = it & 1;
        const u64 nqx2 = f32x2_pack(-qx, -qx);           // p - q == p + (-q)
        const u64 nqy2 = f32x2_pack(-qy, -qy);
        const u64 nqz2 = f32x2_pack(-qz, -qz);

        // ---- distance update + chained argmax (lowest idx on ties) ----
        float bv = -1.0f; int bi = 0;
#pragma unroll
        for (int j = 0; j < FPT / 2; j++) {
            u64 dx = f32x2_add(pxp[j], nqx2);
            u64 dy = f32x2_add(pyp[j], nqy2);
            u64 dz = f32x2_add(pzp[j], nqz2);
            u64 t1 = f32x2_mul(dx, dx);
            u64 t2 = f32x2_mul(dy, dy);
            u64 s1 = f32x2_add(t1, t2);
            u64 t3 = f32x2_mul(dz, dz);
            u64 dd = f32x2_add(s1, t3);
            float d0, d1;
            f32x2_unpack(dd, d0, d1);
            float n0 = fminf(dist[2 * j], d0);
            dist[2 * j] = n0;
            if (n0 > bv) { bv = n0; bi = base + 2 * j; }
            float n1 = fminf(dist[2 * j + 1], d1);
            dist[2 * j + 1] = n1;
            if (n1 > bv) { bv = n1; bi = base + 2 * j + 1; }
        }

        // ---- warp argmax (dist>=0: bits monotone; lane order == index order) ----
        uint32_t bvbits = __float_as_uint(bv);
        uint32_t mx = __reduce_max_sync(0xffffffffu, bvbits);
        uint32_t ball = __ballot_sync(0xffffffffu, bvbits == mx);
        int wbi = __shfl_sync(0xffffffffu, bi, __ffs(ball) - 1);
        if (lane == 0) s_lead[buf][wrp] = make_uint2(mx, (uint32_t)wbi);
        __syncthreads();

        // ---- CTA reduce (redundant in every warp; no 2nd barrier) ----
        uint2 L = (lane < NW) ? s_lead[buf][lane] : make_uint2(0u, 0u);
        uint32_t m2 = __reduce_max_sync(0xffffffffu, L.x);
        uint32_t b2 = __ballot_sync(0xffffffffu, (lane < NW) && (L.x == m2));
        int widx = __shfl_sync(0xffffffffu, (int)L.y, __ffs(b2) - 1);

        // ---- warp 0 sends stamped candidate words to all 4 CTAs ----
        if (wrp == 0 && lane < 16) {
            float4 wv = s_p4[widx];                      // broadcast LDS.128
            int word = lane & 3;
            uint32_t payload = (word == 0) ? m2
                             : (word == 1) ? __float_as_uint(wv.x)
                             : (word == 2) ? __float_as_uint(wv.y)
                             :               __float_as_uint(wv.z);
            u64 w = ((u64)(uint32_t)it << 32) | (u64)payload;
            st_clu_u64(buf ? a_s1 : a_s0, w);
        }

        // ---- every warp polls its local stamped words (lanes 0..15) ----
        uint32_t payload = 0;
        if (lane < 16) {
            uint32_t a = smem_u32(&s_slot[buf][lane >> 2][lane & 3]);
            u64 w;
            do { w = ld_vol_sh_u64(a); } while ((uint32_t)(w >> 32) != (uint32_t)it);
            payload = (uint32_t)w;
        }
        __syncwarp();

        // ---- pick winner among 4 ranks (strict > in rank order == lowest
        //      global index on ties, since rank r owns indices [r*2048, ...)) ----
        uint32_t k0 = __shfl_sync(0xffffffffu, payload, 0);
        uint32_t k1 = __shfl_sync(0xffffffffu, payload, 4);
        uint32_t k2 = __shfl_sync(0xffffffffu, payload, 8);
        uint32_t k3 = __shfl_sync(0xffffffffu, payload, 12);
        uint32_t best = k0; int wr = 0;
        if (k1 > best) { best = k1; wr = 1; }
        if (k2 > best) { best = k2; wr = 2; }
        if (k3 > best) { best = k3; wr = 3; }
        qx = __uint_as_float(__shfl_sync(0xffffffffu, payload, wr * 4 + 1));
        qy = __uint_as_float(__shfl_sync(0xffffffffu, payload, wr * 4 + 2));
        qz = __uint_as_float(__shfl_sync(0xffffffffu, payload, wr * 4 + 3));

        if (r == 0 && t == 0) {
            int o = (b * MP + it) * 3;
            g_newp[o] = qx; g_newp[o + 1] = qy; g_newp[o + 2] = qz;
        }
    }

    asm volatile("barrier.cluster.arrive.aligned;" ::: "memory");
    asm volatile("barrier.cluster.wait.aligned;" ::: "memory");
}

// ---------------- KNN: thread-per-query, 16-entry register heap ----------------
#define KT 2048   // point tile
__global__ void __launch_bounds__(128) knn_kernel() {
    __shared__ __align__(16) float4 tile[KT];
    const int m = blockIdx.x * 128 + threadIdx.x;       // global query id
    const int b = m / MP;

    const float q0 = g_newp[3 * m], q1 = g_newp[3 * m + 1], q2 = g_newp[3 * m + 2];
    const float qq = __fadd_rn(__fadd_rn(__fmul_rn(q0, q0), __fmul_rn(q1, q1)),
                               __fmul_rn(q2, q2));

    float bd[KNN]; int bix[KNN];
#pragma unroll
    for (int s = 0; s < KNN; s++) { bd[s] = 3.402823466e38f; bix[s] = 0x7fffffff; }
    float wv = 3.402823466e38f; int wIdx = 0x7fffffff; int wslot = 0;

    const float4* src = g_pts4 + (size_t)b * NP;
    for (int tb = 0; tb < NP / KT; tb++) {
        for (int j = threadIdx.x; j < KT; j += 128) tile[j] = src[tb * KT + j];
        __syncthreads();
        for (int jj = 0; jj < KT; jj++) {
            float4 p = tile[jj];
            // JAX: d2 = (qq + pp) - 2*(q . p)  with fma-chain dot
            float dot = __fmaf_rn(q2, p.z, __fmaf_rn(q1, p.y, __fmul_rn(q0, p.x)));
            float d2 = __fsub_rn(__fadd_rn(qq, p.w), __fmul_rn(2.0f, dot));
            if (d2 < wv) {                        // strict: ties keep earlier index
                int j = tb * KT + jj;
#pragma unroll
                for (int s = 0; s < KNN; s++)
                    if (s == wslot) { bd[s] = d2; bix[s] = j; }
                wv = bd[0]; wIdx = bix[0]; wslot = 0;
#pragma unroll
                for (int s = 1; s < KNN; s++)
                    if (bd[s] > wv || (bd[s] == wv && bix[s] > wIdx)) {
                        wv = bd[s]; wIdx = bix[s]; wslot = s;
                    }
            }
        }
        __syncthreads();
    }
#pragma unroll
    for (int s = 0; s < KNN; s++) g_nidx[m * KNN + s] = bix[s];
}

// ---------------- group + linear + channel stats + k-max/min -------------------
__global__ void __launch_bounds__(128) group_kernel(const float* __restrict__ feat,
                                                    const float* __restrict__ Wm) {
    __shared__ __align__(16) float sW[CO * CG];
    __shared__ __align__(16) float sg[KNN][CGP];
    __shared__ int snb[KNN];

    const int tid = threadIdx.x;
    const int o = tid;
    for (int j = tid; j < CO * CG; j += 128) sW[j] = Wm[j];
    __syncthreads();

    float w[CGP];
#pragma unroll
    for (int c = 0; c < CG; c++) w[c] = sW[o * CG + c];
    w[CG] = 0.0f;

    double lsum = 0.0, lsq = 0.0;
    const int m0 = blockIdx.x * 8;

    for (int mi = 0; mi < 8; mi++) {
        const int m = m0 + mi;
        const int b = m / MP;
        if (tid < KNN) snb[tid] = g_nidx[m * KNN + tid];
        __syncthreads();

        // relative xyz (JAX-exact sub) + zero pad
        if (tid < KNN) {
            float4 p = g_pts4[(size_t)b * NP + snb[tid]];
            sg[tid][0] = __fsub_rn(p.x, g_newp[3 * m]);
            sg[tid][1] = __fsub_rn(p.y, g_newp[3 * m + 1]);
            sg[tid][2] = __fsub_rn(p.z, g_newp[3 * m + 2]);
            sg[tid][CG] = 0.0f;
        }
        // features: 16 rows x 64, 8 floats per thread
        {
            int k = tid >> 3, c0 = (tid & 7) << 3;
            const float* fr = feat + ((size_t)b * NP + snb[k]) * CIN + c0;
            float4 a = *(const float4*)fr;
            float4 bq = *(const float4*)(fr + 4);
            sg[k][3 + c0 + 0] = a.x;  sg[k][3 + c0 + 1] = a.y;
            sg[k][3 + c0 + 2] = a.z;  sg[k][3 + c0 + 3] = a.w;
            sg[k][3 + c0 + 4] = bq.x; sg[k][3 + c0 + 5] = bq.y;
            sg[k][3 + c0 + 6] = bq.z; sg[k][3 + c0 + 7] = bq.w;
        }
        __syncthreads();

        float ymx = -3.402823466e38f, ymn = 3.402823466e38f;
        float fsum = 0.0f, fsq = 0.0f;     // per-m float partials (16 samples)
#pragma unroll 1
        for (int k = 0; k < KNN; k++) {
            const float4* gr = (const float4*)sg[k];
            float acc = 0.0f;
#pragma unroll
            for (int c4 = 0; c4 < CGP / 4; c4++) {
                float4 gv = gr[c4];
                acc = __fmaf_rn(gv.x, w[4 * c4 + 0], acc);
                acc = __fmaf_rn(gv.y, w[4 * c4 + 1], acc);
                acc = __fmaf_rn(gv.z, w[4 * c4 + 2], acc);
                acc = __fmaf_rn(gv.w, w[4 * c4 + 3], acc);
            }
            ymx = fmaxf(ymx, acc);
            ymn = fminf(ymn, acc);
            fsum = __fadd_rn(fsum, acc);
            fsq = __fmaf_rn(acc, acc, fsq);
        }
        lsum += (double)fsum;
        lsq  += (double)fsq;
        g_ymax[m * CO + o] = ymx;
        g_ymin[m * CO + o] = ymn;
        __syncthreads();
    }
    atomicAdd(&g_sum[o], lsum);
    atomicAdd(&g_sumsq[o], lsq);
}

// ---------------- BN statistics finalize ----------------------------------------
__global__ void stats_kernel(const float* __restrict__ gamma,
                             const float* __restrict__ beta) {
    int o = threadIdx.x;
    if (o >= CO) return;
    const double n = (double)BB * MP * KNN;
    double mean = g_sum[o] / n;
    double var = g_sumsq[o] / n - mean * mean;
    if (var < 0.0) var = 0.0;
    double s = (double)gamma[o] / sqrt(var + EPSBN);
    g_scale[o] = (float)s;
    g_meanv[o] = (float)mean;
    g_shift[o] = beta[o];
}

// ---------------- output: relu(max_k BN(y)) via max/min trick -------------------
__global__ void out_kernel(float* __restrict__ dst) {
    int idx = blockIdx.x * 256 + threadIdx.x;
    if (idx >= BB * MP * CO) return;
    int o = idx & (CO - 1);
    float s = g_scale[o];
    float v = (s >= 0.0f) ? g_ymax[idx] : g_ymin[idx];
    float t = __fsub_rn(v, g_meanv[o]);
    float r = __fadd_rn(__fmul_rn(t, s), g_shift[o]);
    dst[idx] = fmaxf(r, 0.0f);
}

__global__ void copy_np_kernel(float* __restrict__ dst) {
    int i = blockIdx.x * 256 + threadIdx.x;
    if (i < BB * MP * 3) dst[i] = g_newp[i];
}

__global__ void splits_f32_kernel(float* __restrict__ dst) {
    int i = threadIdx.x;
    if (i <= BB) dst[i] = (float)(i * MP);
}
__global__ void splits_i64_kernel(long long* __restrict__ dst) {
    int i = threadIdx.x;
    if (i <= BB) dst[i] = (long long)i * MP;
}

// ---------------- launch ---------------------------------------------------------
extern "C" void kernel_launch(void* const* d_in, const int* in_sizes, int n_in,
                              void* d_out, int out_size) {
    const float* point = (const float*)d_in[0];
    const float* feat  = (const float*)d_in[1];
    const float* Wm    = (const float*)d_in[3];
    const float* gamma = (const float*)d_in[4];
    const float* beta  = (const float*)d_in[5];
    float* out = (float*)d_out;

    init_kernel<<<1, 128>>>();
    prep_kernel<<<(BB * NP + 255) / 256, 256>>>(point);
    fps_kernel<<<BB * CSZ, FTH>>>();
    knn_kernel<<<BB * MP / 128, 128>>>();
    group_kernel<<<BB * MP / 8, 128>>>(feat, Wm);
    stats_kernel<<<1, 128>>>(gamma, beta);

    const int NPT = BB * MP * 3;          // 24576
    const int NFT = BB * MP * CO;         // 1048576
    int feat_off = 0;
    bool write_pts = false;
    if (out_size >= NPT + NFT) { write_pts = true; feat_off = NPT; }

    out_kernel<<<(NFT + 255) / 256, 256>>>(out + feat_off);
    if (write_pts) copy_np_kernel<<<(NPT + 255) / 256, 256>>>(out);

    int rem = out_size - feat_off - NFT;
    if (rem == BB + 1) {
        splits_f32_kernel<<<1, 32>>>(out + feat_off + NFT);
    } else if (rem == 2 * (BB + 1)) {
        splits_i64_kernel<<<1, 32>>>((long long*)(out + feat_off + NFT));
    }
}